// round 1
// baseline (speedup 1.0000x reference)
#include <cuda_runtime.h>

// KREmbedding: Gaussian-weighted context embedding aggregation.
// context: [B, C] int32, center: [B] int32, W: [V, D] float32 -> out [B, D] float32
// B=8192, C=32, D=512, V=50000, SIGMA=1.0
//
// out[b] = sum_c e_c * W[context[b,c]] / (sum_c e_c + 1e-8)
//   where e_c = exp(-||W[context[b,c]] - W[center[b]]||^2 / 2)
// (normalization deferred -> each gathered row is read exactly once)

#define KB_B 8192
#define KB_C 32
#define KB_D 512
#define NWARP 8
#define NTHREADS 256

__global__ __launch_bounds__(NTHREADS, 4)
void kre_kernel(const int* __restrict__ context,
                const int* __restrict__ center,
                const float* __restrict__ W,
                float* __restrict__ out)
{
    const int b    = blockIdx.x;
    const int tid  = threadIdx.x;
    const int lane = tid & 31;
    const int wid  = tid >> 5;

    __shared__ float s_acc[NWARP][KB_D];   // per-warp partial weighted sums (16 KB)
    __shared__ float s_esum[NWARP];

    // ---- load center row into registers (lane-strided float4, coalesced) ----
    const int cen_idx = __ldg(&center[b]);
    const float4* cenp = reinterpret_cast<const float4*>(W + (size_t)cen_idx * KB_D);
    float4 cen[4];
#pragma unroll
    for (int i = 0; i < 4; i++) cen[i] = __ldg(&cenp[lane + 32 * i]);

    // ---- mainloop: each warp processes 4 context rows ----
    float4 acc[4];
#pragma unroll
    for (int i = 0; i < 4; i++) acc[i] = make_float4(0.f, 0.f, 0.f, 0.f);
    float esum = 0.f;

#pragma unroll
    for (int c = wid; c < KB_C; c += NWARP) {
        const int idx = __ldg(&context[b * KB_C + c]);
        const float4* rowp = reinterpret_cast<const float4*>(W + (size_t)idx * KB_D);
        float4 r[4];
#pragma unroll
        for (int i = 0; i < 4; i++) r[i] = __ldg(&rowp[lane + 32 * i]);

        float d2 = 0.f;
#pragma unroll
        for (int i = 0; i < 4; i++) {
            float dx = r[i].x - cen[i].x; d2 = fmaf(dx, dx, d2);
            float dy = r[i].y - cen[i].y; d2 = fmaf(dy, dy, d2);
            float dz = r[i].z - cen[i].z; d2 = fmaf(dz, dz, d2);
            float dw = r[i].w - cen[i].w; d2 = fmaf(dw, dw, d2);
        }
        // warp-reduce the 512-element squared distance
#pragma unroll
        for (int off = 16; off; off >>= 1)
            d2 += __shfl_xor_sync(0xffffffffu, d2, off);

        const float e = __expf(-0.5f * d2);   // underflows to 0 exactly like the fp32 reference
        esum += e;
#pragma unroll
        for (int i = 0; i < 4; i++) {
            acc[i].x = fmaf(e, r[i].x, acc[i].x);
            acc[i].y = fmaf(e, r[i].y, acc[i].y);
            acc[i].z = fmaf(e, r[i].z, acc[i].z);
            acc[i].w = fmaf(e, r[i].w, acc[i].w);
        }
    }

    // ---- spill per-warp partials to smem ----
    float4* sa = reinterpret_cast<float4*>(s_acc[wid]);
#pragma unroll
    for (int i = 0; i < 4; i++) sa[lane + 32 * i] = acc[i];
    if (lane == 0) s_esum[wid] = esum;
    __syncthreads();

    // ---- cross-warp combine + normalized store ----
    float denom = 1e-8f;
#pragma unroll
    for (int w = 0; w < NWARP; w++) denom += s_esum[w];
    const float inv = 1.0f / denom;

#pragma unroll
    for (int d = tid; d < KB_D; d += NTHREADS) {
        float s = 0.f;
#pragma unroll
        for (int w = 0; w < NWARP; w++) s += s_acc[w][d];
        out[(size_t)b * KB_D + d] = s * inv;
    }
}

extern "C" void kernel_launch(void* const* d_in, const int* in_sizes, int n_in,
                              void* d_out, int out_size)
{
    // metadata order: context [B*C] int32, center [B] int32, W [V*D] f32.
    // Be defensive: identify by element count.
    const int* context = (const int*)d_in[0];
    const int* center  = (const int*)d_in[1];
    const float* W     = (const float*)d_in[2];
    for (int i = 0; i < n_in; i++) {
        if (in_sizes[i] == KB_B * KB_C)      context = (const int*)d_in[i];
        else if (in_sizes[i] == KB_B)        center  = (const int*)d_in[i];
        else if (in_sizes[i] > KB_B * KB_C)  W       = (const float*)d_in[i];
    }
    float* out = (float*)d_out;
    kre_kernel<<<KB_B, NTHREADS>>>(context, center, W, out);
}

// round 2
// speedup vs baseline: 1.3578x; 1.3578x over previous
#include <cuda_runtime.h>

// KREmbedding: Gaussian-weighted context embedding aggregation.
// context: [B, C] int32, center: [B] int32, W: [V, D] float32 -> out [B, D] float32
// B=8192, C=32, D=512, SIGMA=1.0
//
// out[b] = sum_c e_c * W[context[b,c]] / (sum_c e_c + 1e-8),
//   e_c = exp(-||W[context[b,c]] - W[center[b]]||^2 / 2)
//
// Round 2 design: ONE WARP PER BATCH ROW.
//  - lane-parallel index load (1 coalesced LDG for all 32 indices) + shfl broadcast
//  - cen/acc register-resident, zero shared memory, zero __syncthreads
//  - unroll 2 so next row's LDGs overlap the current row's shfl-reduce/expf chain

#define KB_B 8192
#define KB_C 32
#define KB_D 512
#define NTHREADS 256
#define WARPS_PER_BLOCK (NTHREADS / 32)

__global__ __launch_bounds__(NTHREADS)
void kre_kernel(const int* __restrict__ context,
                const int* __restrict__ center,
                const float* __restrict__ W,
                float* __restrict__ out)
{
    const int lane = threadIdx.x & 31;
    const int b    = blockIdx.x * WARPS_PER_BLOCK + (threadIdx.x >> 5);
    if (b >= KB_B) return;

    // all 32 context indices for this b in one coalesced load (one per lane)
    const int my_idx  = __ldg(&context[b * KB_C + lane]);
    const int cen_idx = __ldg(&center[b]);

    // center row: 16 floats per lane (lane-strided float4 -> 512B contiguous per LDG)
    const float4* cenp = reinterpret_cast<const float4*>(W + (size_t)cen_idx * KB_D);
    float4 cen[4];
#pragma unroll
    for (int i = 0; i < 4; i++) cen[i] = __ldg(&cenp[lane + 32 * i]);

    float4 acc[4];
#pragma unroll
    for (int i = 0; i < 4; i++) acc[i] = make_float4(0.f, 0.f, 0.f, 0.f);
    float esum = 0.f;

#pragma unroll 2
    for (int c = 0; c < KB_C; c++) {
        const int idx = __shfl_sync(0xffffffffu, my_idx, c);
        const float4* rowp = reinterpret_cast<const float4*>(W + (size_t)idx * KB_D);
        float4 r[4];
#pragma unroll
        for (int i = 0; i < 4; i++) r[i] = __ldg(&rowp[lane + 32 * i]);

        // partial squared distance over this lane's 16 elements
        float d2 = 0.f;
#pragma unroll
        for (int i = 0; i < 4; i++) {
            float dx = r[i].x - cen[i].x; d2 = fmaf(dx, dx, d2);
            float dy = r[i].y - cen[i].y; d2 = fmaf(dy, dy, d2);
            float dz = r[i].z - cen[i].z; d2 = fmaf(dz, dz, d2);
            float dw = r[i].w - cen[i].w; d2 = fmaf(dw, dw, d2);
        }
        // warp-reduce -> full 512-element distance in every lane
#pragma unroll
        for (int off = 16; off; off >>= 1)
            d2 += __shfl_xor_sync(0xffffffffu, d2, off);

        const float e = __expf(-0.5f * d2);  // underflow-to-0 matches fp32 reference
        esum += e;
#pragma unroll
        for (int i = 0; i < 4; i++) {
            acc[i].x = fmaf(e, r[i].x, acc[i].x);
            acc[i].y = fmaf(e, r[i].y, acc[i].y);
            acc[i].z = fmaf(e, r[i].z, acc[i].z);
            acc[i].w = fmaf(e, r[i].w, acc[i].w);
        }
    }

    const float inv = 1.0f / (esum + 1e-8f);
    float4* op = reinterpret_cast<float4*>(out + (size_t)b * KB_D);
#pragma unroll
    for (int i = 0; i < 4; i++) {
        float4 v = acc[i];
        v.x *= inv; v.y *= inv; v.z *= inv; v.w *= inv;
        op[lane + 32 * i] = v;
    }
}

extern "C" void kernel_launch(void* const* d_in, const int* in_sizes, int n_in,
                              void* d_out, int out_size)
{
    const int* context = (const int*)d_in[0];
    const int* center  = (const int*)d_in[1];
    const float* W     = (const float*)d_in[2];
    for (int i = 0; i < n_in; i++) {
        if (in_sizes[i] == KB_B * KB_C)      context = (const int*)d_in[i];
        else if (in_sizes[i] == KB_B)        center  = (const int*)d_in[i];
        else if (in_sizes[i] > KB_B * KB_C)  W       = (const float*)d_in[i];
    }
    float* out = (float*)d_out;
    const int nblocks = (KB_B + WARPS_PER_BLOCK - 1) / WARPS_PER_BLOCK;
    kre_kernel<<<nblocks, NTHREADS>>>(context, center, W, out);
}